// round 9
// baseline (speedup 1.0000x reference)
#include <cuda_runtime.h>
#include <cuda_fp16.h>

#define NN 50000
#define NE 800000
#define IND 64
#define HD 128
#define OD 64
#define BN_EPS 1e-5f
#define NB 49   // ceil(NN/1024)

typedef unsigned long long ull;

// ---- scratch (__device__ globals; zero-init at load; zero-invariants kept) ----
__device__ __align__(256) int    g_degi[NN];        // zero-invariant (restored in k_scan3)
__device__ __align__(256) int    g_off[NN + 1];
__device__ __align__(256) int    g_cur[NN];
__device__ __align__(256) int    g_esrc[NE];
__device__ __align__(256) int    g_bsums[NB];
__device__ __align__(256) float  g_deginv[NN];
__device__ __align__(256) __half g_xh[NN * IND];    // fp16 x (gather side)
__device__ __align__(256) float  g_hpre[NN * HD];   // fp32 pre-BN layer-1 out
__device__ __align__(256) __half g_hrelu[NN * HD];  // fp16 relu(bn(hpre))
__device__ __align__(256) float  g_bnsum[HD];       // zero-invariant (restored in k_al2)
__device__ __align__(256) float  g_bnsq[HD];        // zero-invariant (restored in k_al2)
__device__ __align__(256) float  g_scale[HD];
__device__ __align__(256) float  g_shift[HD];
// packed weight pairs: (W[2k][j], W[2k+1][j]) as f32x2
__device__ __align__(256) ull    g_w1l[(IND / 2) * HD];
__device__ __align__(256) ull    g_w1r[(IND / 2) * HD];
__device__ __align__(256) ull    g_w2l[(HD / 2) * OD];
__device__ __align__(256) ull    g_w2r[(HD / 2) * OD];

__device__ __forceinline__ ull pack2(float x, float y) {
    ull r;
    asm("mov.b64 %0, {%1,%2};" : "=l"(r) : "f"(x), "f"(y));
    return r;
}
__device__ __forceinline__ float2 unpack2(ull v) {
    float2 r;
    asm("mov.b64 {%0,%1}, %2;" : "=f"(r.x), "=f"(r.y) : "l"(v));
    return r;
}
__device__ __forceinline__ void ffma2(ull& d, ull a, ull b) {
    asm("fma.rn.f32x2 %0, %1, %2, %0;" : "+l"(d) : "l"(a), "l"(b));
}
__device__ __forceinline__ void fadd2(ull& d, ull a) {
    asm("add.rn.f32x2 %0, %0, %1;" : "+l"(d) : "l"(a));
}
// accumulate 8 fp16 features (one uint4) into 4 f32x2 accumulators
__device__ __forceinline__ void acc_u4(ull* acc, uint4 u) {
    float2 f0 = __half22float2(*(__half2*)&u.x);
    float2 f1 = __half22float2(*(__half2*)&u.y);
    float2 f2 = __half22float2(*(__half2*)&u.z);
    float2 f3 = __half22float2(*(__half2*)&u.w);
    fadd2(acc[0], pack2(f0.x, f0.y));
    fadd2(acc[1], pack2(f1.x, f1.y));
    fadd2(acc[2], pack2(f2.x, f2.y));
    fadd2(acc[3], pack2(f3.x, f3.y));
}
__device__ __forceinline__ uint4 f8_to_h8(const float* s) {
    __half2 a = __floats2half2_rn(s[0], s[1]);
    __half2 b = __floats2half2_rn(s[2], s[3]);
    __half2 c = __floats2half2_rn(s[4], s[5]);
    __half2 d = __floats2half2_rn(s[6], s[7]);
    uint4 u;
    u.x = *(unsigned int*)&a; u.y = *(unsigned int*)&b;
    u.z = *(unsigned int*)&c; u.w = *(unsigned int*)&d;
    return u;
}

// ---- fused prep + degree histogram ----
__global__ void k_prepdeg(const float* __restrict__ x,
                          const float* __restrict__ W1l, const float* __restrict__ W1r,
                          const float* __restrict__ W2l, const float* __restrict__ W2r,
                          const int* __restrict__ dst) {
    int t = blockIdx.x * blockDim.x + threadIdx.x;
    int stride = gridDim.x * blockDim.x;
    for (int i = t; i < (IND / 2) * HD; i += stride) {
        int kp = i >> 7, j = i & 127;
        g_w1l[i] = pack2(W1l[(2 * kp) * HD + j], W1l[(2 * kp + 1) * HD + j]);
        g_w1r[i] = pack2(W1r[(2 * kp) * HD + j], W1r[(2 * kp + 1) * HD + j]);
    }
    for (int i = t; i < (HD / 2) * OD; i += stride) {
        int kp = i >> 6, j = i & 63;
        g_w2l[i] = pack2(W2l[(2 * kp) * OD + j], W2l[(2 * kp + 1) * OD + j]);
        g_w2r[i] = pack2(W2r[(2 * kp) * OD + j], W2r[(2 * kp + 1) * OD + j]);
    }
    for (int i = t; i < NN * IND / 8; i += stride) {
        float4 v0 = ((const float4*)x)[2 * i];
        float4 v1 = ((const float4*)x)[2 * i + 1];
        float f[8] = {v0.x, v0.y, v0.z, v0.w, v1.x, v1.y, v1.z, v1.w};
        ((uint4*)g_xh)[i] = f8_to_h8(f);
    }
    for (int i = t; i < NE / 4; i += stride) {
        int4 d = ((const int4*)dst)[i];
        atomicAdd(&g_degi[d.x], 1);
        atomicAdd(&g_degi[d.y], 1);
        atomicAdd(&g_degi[d.z], 1);
        atomicAdd(&g_degi[d.w], 1);
    }
}

// ---- scan stage 1 ----
__global__ void k_scan1() {
    __shared__ int ws[32];
    int tid = threadIdx.x, lane = tid & 31, w = tid >> 5;
    int i = blockIdx.x * 1024 + tid;
    int v = (i < NN) ? g_degi[i] : 0;
    int s = v;
#pragma unroll
    for (int o = 1; o < 32; o <<= 1) {
        int tt = __shfl_up_sync(0xffffffffu, s, o);
        if (lane >= o) s += tt;
    }
    if (lane == 31) ws[w] = s;
    __syncthreads();
    if (w == 0) {
        int t2 = ws[lane];
#pragma unroll
        for (int o = 1; o < 32; o <<= 1) {
            int tt = __shfl_up_sync(0xffffffffu, t2, o);
            if (lane >= o) t2 += tt;
        }
        ws[lane] = t2;
    }
    __syncthreads();
    int excl = ((w > 0) ? ws[w - 1] : 0) + s - v;
    if (i < NN) g_off[i] = excl;
    if (tid == 1023) g_bsums[blockIdx.x] = ws[31];
}

// ---- scan stage 2: prefix + cursors + deginv + restore g_degi zeros ----
__global__ void k_scan3() {
    __shared__ int sb[64];
    int tid = threadIdx.x;
    if (tid < 64) {
        int lane = tid & 31;
        int v = (tid < NB) ? g_bsums[tid] : 0;
        int s = v;
#pragma unroll
        for (int o = 1; o < 32; o <<= 1) {
            int tt = __shfl_up_sync(0xffffffffu, s, o);
            if (lane >= o) s += tt;
        }
        sb[tid] = s - v;
    }
    __syncthreads();
    if (tid >= 32 && tid < 64) {
        int w0tot = sb[31] + g_bsums[31];
        sb[tid] += w0tot;
    }
    __syncthreads();
    int pref = sb[blockIdx.x];
    int i = blockIdx.x * 1024 + tid;
    if (i < NN) {
        int off = g_off[i] + pref;
        g_off[i] = off;
        g_cur[i] = off;
        int d = g_degi[i];
        g_deginv[i] = (d > 0) ? (1.0f / (float)d) : 0.0f;
        g_degi[i] = 0;
    }
    if (i == NN) g_off[NN] = NE;
}

// ---- CSR fill, 4 edges/thread ----
__global__ void k_fill(const int* __restrict__ src, const int* __restrict__ dst) {
    int t = blockIdx.x * blockDim.x + threadIdx.x;
    if (t * 4 >= NE) return;
    int4 s4 = ((const int4*)src)[t];
    int4 d4 = ((const int4*)dst)[t];
    int p0 = atomicAdd(&g_cur[d4.x], 1);
    int p1 = atomicAdd(&g_cur[d4.y], 1);
    int p2 = atomicAdd(&g_cur[d4.z], 1);
    int p3 = atomicAdd(&g_cur[d4.w], 1);
    g_esrc[p0] = s4.x;
    g_esrc[p1] = s4.y;
    g_esrc[p2] = s4.z;
    g_esrc[p3] = s4.w;
}

// ==== FUSED layer 1: per-block aggregate (agg1) + FFMA2 GEMM + BN partials ====
#define NT1 32
__global__ void __launch_bounds__(256) k_al1(const float* __restrict__ x,
                                             const float* __restrict__ b1) {
    __shared__ float sa[NT1][IND];   // mean-aggregated neighbors (fp32)
    __shared__ float sx[NT1][IND];   // root features (fp32)
    const int n0 = blockIdx.x * NT1;
    const int tid = threadIdx.x;     // 256

    // ---- phase 1: gather-aggregate 32 nodes, 8 threads/node, 8 feats/thread ----
    {
        int g = tid >> 3;            // node slot 0..31
        int c = tid & 7;             // uint4 chunk (features 8c..8c+7)
        int node = n0 + g;
        ull acc[4] = {0ull, 0ull, 0ull, 0ull};
        float di = 0.f;
        if (node < NN) {
            int beg = g_off[node], end = g_off[node + 1];
            di = g_deginv[node];
            int j = beg;
            for (; j + 2 <= end; j += 2) {
                uint4 u0 = ((const uint4*)g_xh)[g_esrc[j] * 8 + c];
                uint4 u1 = ((const uint4*)g_xh)[g_esrc[j + 1] * 8 + c];
                acc_u4(acc, u0);
                acc_u4(acc, u1);
            }
            if (j < end)
                acc_u4(acc, ((const uint4*)g_xh)[g_esrc[j] * 8 + c]);
        }
        float2 p0 = unpack2(acc[0]), p1 = unpack2(acc[1]);
        float2 p2 = unpack2(acc[2]), p3 = unpack2(acc[3]);
        *(float4*)&sa[g][8 * c]     = make_float4(p0.x * di, p0.y * di, p1.x * di, p1.y * di);
        *(float4*)&sa[g][8 * c + 4] = make_float4(p2.x * di, p2.y * di, p3.x * di, p3.y * di);
        // root tile
        float4 vx0 = make_float4(0.f, 0.f, 0.f, 0.f), vx1 = vx0;
        if (node < NN) {
            vx0 = ((const float4*)x)[node * 16 + 2 * c];
            vx1 = ((const float4*)x)[node * 16 + 2 * c + 1];
        }
        *(float4*)&sx[g][8 * c]     = vx0;
        *(float4*)&sx[g][8 * c + 4] = vx1;
    }
    __syncthreads();

    // ---- phase 2: FFMA2 GEMM, 256 threads = 128 features x 2 node-halves ----
    const int j = tid & 127;
    const int bn = (tid >> 7) << 4;  // 0 or 16
    ull acc[16];
#pragma unroll
    for (int n = 0; n < 16; n++) acc[n] = 0ull;

    for (int kq = 0; kq < IND / 4; kq++) {
        ull wl01 = g_w1l[(2 * kq) * HD + j];
        ull wl23 = g_w1l[(2 * kq + 1) * HD + j];
        ull wr01 = g_w1r[(2 * kq) * HD + j];
        ull wr23 = g_w1r[(2 * kq + 1) * HD + j];
#pragma unroll
        for (int n = 0; n < 16; n++) {
            ulonglong2 a = *(const ulonglong2*)&sa[bn + n][4 * kq];
            ulonglong2 xx = *(const ulonglong2*)&sx[bn + n][4 * kq];
            ffma2(acc[n], a.x, wl01);
            ffma2(acc[n], a.y, wl23);
            ffma2(acc[n], xx.x, wr01);
            ffma2(acc[n], xx.y, wr23);
        }
    }

    const float bj = b1[j];
    float s = 0.f, sq = 0.f;
#pragma unroll
    for (int n = 0; n < 16; n++) {
        int node = n0 + bn + n;
        if (node < NN) {
            float2 p = unpack2(acc[n]);
            float v = p.x + p.y + bj;
            g_hpre[node * HD + j] = v;
            s += v;
            sq += v * v;
        }
    }
    atomicAdd(&g_bnsum[j], s);
    atomicAdd(&g_bnsq[j], sq);
}

// ---- BN finalize + relu: g_hrelu = fp16(relu(bn(hpre))) ----
__global__ void k_hrelu(const float* __restrict__ gamma,
                        const float* __restrict__ beta) {
    __shared__ float s_sc[HD];
    __shared__ float s_sh[HD];
    int tid = threadIdx.x;
    if (tid < HD) {
        float mu = g_bnsum[tid] * (1.0f / NN);
        float var = g_bnsq[tid] * (1.0f / NN) - mu * mu;
        float sc = gamma[tid] * rsqrtf(var + BN_EPS);
        float sh = beta[tid] - mu * sc;
        s_sc[tid] = sc;
        s_sh[tid] = sh;
        if (blockIdx.x == 0) { g_scale[tid] = sc; g_shift[tid] = sh; }
    }
    __syncthreads();
    int i = blockIdx.x * blockDim.x + tid;   // over NN*HD/4 float4s
    if (i >= NN * HD / 4) return;
    int c = i & 31;
    float4 h = ((const float4*)g_hpre)[i];
    float4 sc = *(const float4*)&s_sc[4 * c];
    float4 sh = *(const float4*)&s_sh[4 * c];
    float v0 = fmaxf(fmaf(h.x, sc.x, sh.x), 0.f);
    float v1 = fmaxf(fmaf(h.y, sc.y, sh.y), 0.f);
    float v2 = fmaxf(fmaf(h.z, sc.z, sh.z), 0.f);
    float v3 = fmaxf(fmaf(h.w, sc.w, sh.w), 0.f);
    __half2 a = __floats2half2_rn(v0, v1);
    __half2 b = __floats2half2_rn(v2, v3);
    uint2 u;
    u.x = *(unsigned int*)&a;
    u.y = *(unsigned int*)&b;
    ((uint2*)g_hrelu)[i] = u;
}

// ==== FUSED layer 2: per-block aggregate (agg2) + FFMA2 GEMM -> out;
//      block 0 restores the g_bnsum/g_bnsq zero-invariant (last reader was k_hrelu) ====
#define NT2 32
__global__ void __launch_bounds__(256) k_al2(const float* __restrict__ b2,
                                             float* __restrict__ out) {
    __shared__ float sg[NT2][HD];    // mean-aggregated relu(bn(h)) (fp32)
    __shared__ float sh_[NT2][HD];   // root relu(bn(hpre)) recomputed fp32
    const int n0 = blockIdx.x * NT2;
    const int tid = threadIdx.x;     // 256

    // restore zero-invariant for next kernel_launch call
    if (blockIdx.x == 0 && tid < HD) { g_bnsum[tid] = 0.f; g_bnsq[tid] = 0.f; }

    // ---- phase 1a: gather-aggregate, 16 threads/node, 2 passes of 16 nodes ----
    {
        int c = tid & 15;            // uint4 chunk (features 8c..8c+7 of 128)
        int gbase = tid >> 4;        // 0..15
#pragma unroll
        for (int p = 0; p < 2; p++) {
            int g = gbase + p * 16;  // node slot 0..31
            int node = n0 + g;
            ull acc[4] = {0ull, 0ull, 0ull, 0ull};
            float di = 0.f;
            if (node < NN) {
                int beg = g_off[node], end = g_off[node + 1];
                di = g_deginv[node];
                int j = beg;
                for (; j + 2 <= end; j += 2) {
                    uint4 u0 = ((const uint4*)g_hrelu)[g_esrc[j] * 16 + c];
                    uint4 u1 = ((const uint4*)g_hrelu)[g_esrc[j + 1] * 16 + c];
                    acc_u4(acc, u0);
                    acc_u4(acc, u1);
                }
                if (j < end)
                    acc_u4(acc, ((const uint4*)g_hrelu)[g_esrc[j] * 16 + c]);
            }
            float2 p0 = unpack2(acc[0]), p1 = unpack2(acc[1]);
            float2 p2 = unpack2(acc[2]), p3 = unpack2(acc[3]);
            *(float4*)&sg[g][8 * c]     = make_float4(p0.x * di, p0.y * di, p1.x * di, p1.y * di);
            *(float4*)&sg[g][8 * c + 4] = make_float4(p2.x * di, p2.y * di, p3.x * di, p3.y * di);
        }
    }
    // ---- phase 1b: root tile = relu(bn(hpre)) fp32 ----
    for (int idx = tid; idx < NT2 * (HD / 4); idx += 256) {
        int r = idx >> 5, c = idx & 31;
        int node = n0 + r;
        float4 vh = make_float4(0.f, 0.f, 0.f, 0.f);
        if (node < NN) {
            float4 h  = ((const float4*)g_hpre)[node * 32 + c];
            float4 sc = ((const float4*)g_scale)[c];
            float4 sf = ((const float4*)g_shift)[c];
            vh.x = fmaxf(fmaf(h.x, sc.x, sf.x), 0.f);
            vh.y = fmaxf(fmaf(h.y, sc.y, sf.y), 0.f);
            vh.z = fmaxf(fmaf(h.z, sc.z, sf.z), 0.f);
            vh.w = fmaxf(fmaf(h.w, sc.w, sf.w), 0.f);
        }
        *(float4*)&sh_[r][4 * c] = vh;
    }
    __syncthreads();

    // ---- phase 2: FFMA2 GEMM, 256 threads = 64 features x 4 node-quarters ----
    const int j = tid & 63;
    const int bn = (tid >> 6) << 3;  // 0,8,16,24
    ull acc[8];
#pragma unroll
    for (int n = 0; n < 8; n++) acc[n] = 0ull;

    for (int kq = 0; kq < HD / 4; kq++) {
        ull wl01 = g_w2l[(2 * kq) * OD + j];
        ull wl23 = g_w2l[(2 * kq + 1) * OD + j];
        ull wr01 = g_w2r[(2 * kq) * OD + j];
        ull wr23 = g_w2r[(2 * kq + 1) * OD + j];
#pragma unroll
        for (int n = 0; n < 8; n++) {
            ulonglong2 a = *(const ulonglong2*)&sg[bn + n][4 * kq];
            ulonglong2 h = *(const ulonglong2*)&sh_[bn + n][4 * kq];
            ffma2(acc[n], a.x, wl01);
            ffma2(acc[n], a.y, wl23);
            ffma2(acc[n], h.x, wr01);
            ffma2(acc[n], h.y, wr23);
        }
    }

    const float bj = b2[j];
#pragma unroll
    for (int n = 0; n < 8; n++) {
        int node = n0 + bn + n;
        if (node < NN) {
            float2 p = unpack2(acc[n]);
            out[node * OD + j] = p.x + p.y + bj;
        }
    }
}

extern "C" void kernel_launch(void* const* d_in, const int* in_sizes, int n_in,
                              void* d_out, int out_size) {
    const float* x     = (const float*)d_in[0];
    const int*   ei    = (const int*)d_in[1];
    const float* W1l   = (const float*)d_in[2];
    const float* b1    = (const float*)d_in[3];
    const float* W1r   = (const float*)d_in[4];
    const float* gamma = (const float*)d_in[5];
    const float* beta  = (const float*)d_in[6];
    const float* W2l   = (const float*)d_in[7];
    const float* b2    = (const float*)d_in[8];
    const float* W2r   = (const float*)d_in[9];
    float* out = (float*)d_out;

    const int* src = ei;
    const int* dst = ei + NE;

    k_prepdeg<<<2048, 256>>>(x, W1l, W1r, W2l, W2r, dst);
    k_scan1<<<NB, 1024>>>();
    k_scan3<<<NB, 1024>>>();
    k_fill<<<(NE / 4 + 255) / 256, 256>>>(src, dst);
    k_al1<<<(NN + NT1 - 1) / NT1, 256>>>(x, b1);
    k_hrelu<<<(NN * HD / 4 + 255) / 256, 256>>>(gamma, beta);
    k_al2<<<(NN + NT2 - 1) / NT2, 256>>>(b2, out);
}

// round 10
// speedup vs baseline: 1.0673x; 1.0673x over previous
#include <cuda_runtime.h>
#include <cuda_fp16.h>

#define NN 50000
#define NE 800000
#define IND 64
#define HD 128
#define OD 64
#define BN_EPS 1e-5f
#define NB 49   // ceil(NN/1024)

typedef unsigned long long ull;

// ---- scratch (__device__ globals; zero-init at load; zero-invariants kept) ----
__device__ __align__(256) int    g_degi[NN];        // zero-invariant (restored in k_scan3)
__device__ __align__(256) int    g_off[NN + 1];
__device__ __align__(256) int    g_cur[NN];
__device__ __align__(256) int    g_esrc[NE];
__device__ __align__(256) int    g_bsums[NB];
__device__ __align__(256) float  g_deginv[NN];
__device__ __align__(256) __half g_xh[NN * IND];    // fp16 x (gather side)
__device__ __align__(256) float  g_agg1[NN * IND];  // fp32 mean-agg of x
__device__ __align__(256) float  g_hpre[NN * HD];   // fp32 pre-BN layer-1 out
__device__ __align__(256) __half g_hrelu[NN * HD];  // fp16 relu(bn(hpre))
__device__ __align__(256) float  g_agg2[NN * HD];   // fp32 mean-agg of hrelu
__device__ __align__(256) float  g_bnsum[HD];       // zero-invariant (restored in k_agg2)
__device__ __align__(256) float  g_bnsq[HD];        // zero-invariant (restored in k_agg2)
__device__ __align__(256) float  g_scale[HD];
__device__ __align__(256) float  g_shift[HD];
// packed weight pairs: (W[2k][j], W[2k+1][j]) as f32x2
__device__ __align__(256) ull    g_w1l[(IND / 2) * HD];
__device__ __align__(256) ull    g_w1r[(IND / 2) * HD];
__device__ __align__(256) ull    g_w2l[(HD / 2) * OD];
__device__ __align__(256) ull    g_w2r[(HD / 2) * OD];

__device__ __forceinline__ ull pack2(float x, float y) {
    ull r;
    asm("mov.b64 %0, {%1,%2};" : "=l"(r) : "f"(x), "f"(y));
    return r;
}
__device__ __forceinline__ float2 unpack2(ull v) {
    float2 r;
    asm("mov.b64 {%0,%1}, %2;" : "=f"(r.x), "=f"(r.y) : "l"(v));
    return r;
}
__device__ __forceinline__ void ffma2(ull& d, ull a, ull b) {
    asm("fma.rn.f32x2 %0, %1, %2, %0;" : "+l"(d) : "l"(a), "l"(b));
}
__device__ __forceinline__ void fadd2(ull& d, ull a) {
    asm("add.rn.f32x2 %0, %0, %1;" : "+l"(d) : "l"(a));
}
// accumulate 8 fp16 features (one uint4) into 4 f32x2 accumulators
__device__ __forceinline__ void acc_u4(ull* acc, uint4 u) {
    float2 f0 = __half22float2(*(__half2*)&u.x);
    float2 f1 = __half22float2(*(__half2*)&u.y);
    float2 f2 = __half22float2(*(__half2*)&u.z);
    float2 f3 = __half22float2(*(__half2*)&u.w);
    fadd2(acc[0], pack2(f0.x, f0.y));
    fadd2(acc[1], pack2(f1.x, f1.y));
    fadd2(acc[2], pack2(f2.x, f2.y));
    fadd2(acc[3], pack2(f3.x, f3.y));
}
__device__ __forceinline__ uint4 f8_to_h8(const float* s) {
    __half2 a = __floats2half2_rn(s[0], s[1]);
    __half2 b = __floats2half2_rn(s[2], s[3]);
    __half2 c = __floats2half2_rn(s[4], s[5]);
    __half2 d = __floats2half2_rn(s[6], s[7]);
    uint4 u;
    u.x = *(unsigned int*)&a; u.y = *(unsigned int*)&b;
    u.z = *(unsigned int*)&c; u.w = *(unsigned int*)&d;
    return u;
}

// ---- prep only: weight packing + x -> fp16 (runs on side stream) ----
__global__ void k_prep(const float* __restrict__ x,
                       const float* __restrict__ W1l, const float* __restrict__ W1r,
                       const float* __restrict__ W2l, const float* __restrict__ W2r) {
    int t = blockIdx.x * blockDim.x + threadIdx.x;
    int stride = gridDim.x * blockDim.x;
    for (int i = t; i < (IND / 2) * HD; i += stride) {
        int kp = i >> 7, j = i & 127;
        g_w1l[i] = pack2(W1l[(2 * kp) * HD + j], W1l[(2 * kp + 1) * HD + j]);
        g_w1r[i] = pack2(W1r[(2 * kp) * HD + j], W1r[(2 * kp + 1) * HD + j]);
    }
    for (int i = t; i < (HD / 2) * OD; i += stride) {
        int kp = i >> 6, j = i & 63;
        g_w2l[i] = pack2(W2l[(2 * kp) * OD + j], W2l[(2 * kp + 1) * OD + j]);
        g_w2r[i] = pack2(W2r[(2 * kp) * OD + j], W2r[(2 * kp + 1) * OD + j]);
    }
    for (int i = t; i < NN * IND / 8; i += stride) {
        float4 v0 = ((const float4*)x)[2 * i];
        float4 v1 = ((const float4*)x)[2 * i + 1];
        float f[8] = {v0.x, v0.y, v0.z, v0.w, v1.x, v1.y, v1.z, v1.w};
        ((uint4*)g_xh)[i] = f8_to_h8(f);
    }
}

// ---- degree histogram, 4 edges/thread (main stream, overlaps k_prep) ----
__global__ void k_deg(const int* __restrict__ dst) {
    int t = blockIdx.x * blockDim.x + threadIdx.x;
    if (t * 4 >= NE) return;
    int4 d = ((const int4*)dst)[t];
    atomicAdd(&g_degi[d.x], 1);
    atomicAdd(&g_degi[d.y], 1);
    atomicAdd(&g_degi[d.z], 1);
    atomicAdd(&g_degi[d.w], 1);
}

// ---- scan stage 1 ----
__global__ void k_scan1() {
    __shared__ int ws[32];
    int tid = threadIdx.x, lane = tid & 31, w = tid >> 5;
    int i = blockIdx.x * 1024 + tid;
    int v = (i < NN) ? g_degi[i] : 0;
    int s = v;
#pragma unroll
    for (int o = 1; o < 32; o <<= 1) {
        int tt = __shfl_up_sync(0xffffffffu, s, o);
        if (lane >= o) s += tt;
    }
    if (lane == 31) ws[w] = s;
    __syncthreads();
    if (w == 0) {
        int t2 = ws[lane];
#pragma unroll
        for (int o = 1; o < 32; o <<= 1) {
            int tt = __shfl_up_sync(0xffffffffu, t2, o);
            if (lane >= o) t2 += tt;
        }
        ws[lane] = t2;
    }
    __syncthreads();
    int excl = ((w > 0) ? ws[w - 1] : 0) + s - v;
    if (i < NN) g_off[i] = excl;
    if (tid == 1023) g_bsums[blockIdx.x] = ws[31];
}

// ---- scan stage 2: prefix + cursors + deginv + restore g_degi zeros ----
__global__ void k_scan3() {
    __shared__ int sb[64];
    int tid = threadIdx.x;
    if (tid < 64) {
        int lane = tid & 31;
        int v = (tid < NB) ? g_bsums[tid] : 0;
        int s = v;
#pragma unroll
        for (int o = 1; o < 32; o <<= 1) {
            int tt = __shfl_up_sync(0xffffffffu, s, o);
            if (lane >= o) s += tt;
        }
        sb[tid] = s - v;
    }
    __syncthreads();
    if (tid >= 32 && tid < 64) {
        int w0tot = sb[31] + g_bsums[31];
        sb[tid] += w0tot;
    }
    __syncthreads();
    int pref = sb[blockIdx.x];
    int i = blockIdx.x * 1024 + tid;
    if (i < NN) {
        int off = g_off[i] + pref;
        g_off[i] = off;
        g_cur[i] = off;
        int d = g_degi[i];
        g_deginv[i] = (d > 0) ? (1.0f / (float)d) : 0.0f;
        g_degi[i] = 0;
    }
    if (i == NN) g_off[NN] = NE;
}

// ---- CSR fill, 4 edges/thread ----
__global__ void k_fill(const int* __restrict__ src, const int* __restrict__ dst) {
    int t = blockIdx.x * blockDim.x + threadIdx.x;
    if (t * 4 >= NE) return;
    int4 s4 = ((const int4*)src)[t];
    int4 d4 = ((const int4*)dst)[t];
    int p0 = atomicAdd(&g_cur[d4.x], 1);
    int p1 = atomicAdd(&g_cur[d4.y], 1);
    int p2 = atomicAdd(&g_cur[d4.z], 1);
    int p3 = atomicAdd(&g_cur[d4.w], 1);
    g_esrc[p0] = s4.x;
    g_esrc[p1] = s4.y;
    g_esrc[p2] = s4.z;
    g_esrc[p3] = s4.w;
}

// ---- layer-1 mean aggregation: 8 threads/node, f32x2 accumulate, unroll x2 ----
__global__ void k_agg1() {
    int t = blockIdx.x * blockDim.x + threadIdx.x;
    int node = t >> 3, c = t & 7;
    if (node >= NN) return;
    int beg = g_off[node], end = g_off[node + 1];
    ull acc[4] = {0ull, 0ull, 0ull, 0ull};
    int j = beg;
    for (; j + 2 <= end; j += 2) {
        int s0 = g_esrc[j], s1 = g_esrc[j + 1];
        uint4 u0 = ((const uint4*)g_xh)[s0 * 8 + c];
        uint4 u1 = ((const uint4*)g_xh)[s1 * 8 + c];
        acc_u4(acc, u0);
        acc_u4(acc, u1);
    }
    if (j < end)
        acc_u4(acc, ((const uint4*)g_xh)[g_esrc[j] * 8 + c]);
    float di = g_deginv[node];
    float2 p0 = unpack2(acc[0]), p1 = unpack2(acc[1]);
    float2 p2 = unpack2(acc[2]), p3 = unpack2(acc[3]);
    ((float4*)g_agg1)[node * (IND / 4) + c * 2 + 0] =
        make_float4(p0.x * di, p0.y * di, p1.x * di, p1.y * di);
    ((float4*)g_agg1)[node * (IND / 4) + c * 2 + 1] =
        make_float4(p2.x * di, p2.y * di, p3.x * di, p3.y * di);
}

// ---- layer-1 dense (FFMA2): h_pre = agg1@W1l + b1 + x@W1r ; BN partials ----
#define NT1 32
__global__ void __launch_bounds__(128) k_lin1(const float* __restrict__ x,
                                              const float* __restrict__ b1) {
    __shared__ float sa[NT1][IND];
    __shared__ float sx[NT1][IND];
    const int n0 = blockIdx.x * NT1;
    const int tid = threadIdx.x;   // 128

    for (int idx = tid; idx < NT1 * (IND / 4); idx += 128) {
        int r = idx >> 4, c = idx & 15;
        int node = n0 + r;
        float4 va = make_float4(0.f, 0.f, 0.f, 0.f), vx = va;
        if (node < NN) {
            va = ((const float4*)g_agg1)[node * 16 + c];
            vx = ((const float4*)x)[node * 16 + c];
        }
        *(float4*)&sa[r][4 * c] = va;
        *(float4*)&sx[r][4 * c] = vx;
    }
    __syncthreads();

    const int j = tid;   // 0..127
    ull acc[NT1];
#pragma unroll
    for (int n = 0; n < NT1; n++) acc[n] = 0ull;

    for (int kq = 0; kq < IND / 4; kq++) {
        ull wl01 = g_w1l[(2 * kq) * HD + j];
        ull wl23 = g_w1l[(2 * kq + 1) * HD + j];
        ull wr01 = g_w1r[(2 * kq) * HD + j];
        ull wr23 = g_w1r[(2 * kq + 1) * HD + j];
#pragma unroll
        for (int n = 0; n < NT1; n++) {
            ulonglong2 a = *(const ulonglong2*)&sa[n][4 * kq];
            ulonglong2 xx = *(const ulonglong2*)&sx[n][4 * kq];
            ffma2(acc[n], a.x, wl01);
            ffma2(acc[n], a.y, wl23);
            ffma2(acc[n], xx.x, wr01);
            ffma2(acc[n], xx.y, wr23);
        }
    }

    const float bj = b1[j];
    float s = 0.f, sq = 0.f;
#pragma unroll
    for (int n = 0; n < NT1; n++) {
        int node = n0 + n;
        if (node < NN) {
            float2 p = unpack2(acc[n]);
            float v = p.x + p.y + bj;
            g_hpre[node * HD + j] = v;
            s += v;
            sq += v * v;
        }
    }
    atomicAdd(&g_bnsum[j], s);
    atomicAdd(&g_bnsq[j], sq);
}

// ---- BN finalize + relu: g_hrelu = fp16(relu(bn(hpre))) ----
__global__ void k_hrelu(const float* __restrict__ gamma,
                        const float* __restrict__ beta) {
    __shared__ float s_sc[HD];
    __shared__ float s_sh[HD];
    int tid = threadIdx.x;
    if (tid < HD) {
        float mu = g_bnsum[tid] * (1.0f / NN);
        float var = g_bnsq[tid] * (1.0f / NN) - mu * mu;
        float sc = gamma[tid] * rsqrtf(var + BN_EPS);
        float sh = beta[tid] - mu * sc;
        s_sc[tid] = sc;
        s_sh[tid] = sh;
        if (blockIdx.x == 0) { g_scale[tid] = sc; g_shift[tid] = sh; }
    }
    __syncthreads();
    int i = blockIdx.x * blockDim.x + tid;   // over NN*HD/4 float4s
    if (i >= NN * HD / 4) return;
    int c = i & 31;
    float4 h = ((const float4*)g_hpre)[i];
    float4 sc = *(const float4*)&s_sc[4 * c];
    float4 sh = *(const float4*)&s_sh[4 * c];
    float v0 = fmaxf(fmaf(h.x, sc.x, sh.x), 0.f);
    float v1 = fmaxf(fmaf(h.y, sc.y, sh.y), 0.f);
    float v2 = fmaxf(fmaf(h.z, sc.z, sh.z), 0.f);
    float v3 = fmaxf(fmaf(h.w, sc.w, sh.w), 0.f);
    __half2 a = __floats2half2_rn(v0, v1);
    __half2 b = __floats2half2_rn(v2, v3);
    uint2 u;
    u.x = *(unsigned int*)&a;
    u.y = *(unsigned int*)&b;
    ((uint2*)g_hrelu)[i] = u;
}

// ---- layer-2 mean aggregation: 16 threads/node, f32x2 accumulate, unroll x2;
//      restores g_bnsum/g_bnsq zero-invariant ----
__global__ void k_agg2() {
    int t = blockIdx.x * blockDim.x + threadIdx.x;
    if (t < HD) { g_bnsum[t] = 0.f; g_bnsq[t] = 0.f; }
    int node = t >> 4, c = t & 15;
    if (node >= NN) return;
    int beg = g_off[node], end = g_off[node + 1];
    ull acc[4] = {0ull, 0ull, 0ull, 0ull};
    int j = beg;
    for (; j + 2 <= end; j += 2) {
        int s0 = g_esrc[j], s1 = g_esrc[j + 1];
        uint4 u0 = ((const uint4*)g_hrelu)[s0 * 16 + c];
        uint4 u1 = ((const uint4*)g_hrelu)[s1 * 16 + c];
        acc_u4(acc, u0);
        acc_u4(acc, u1);
    }
    if (j < end)
        acc_u4(acc, ((const uint4*)g_hrelu)[g_esrc[j] * 16 + c]);
    float di = g_deginv[node];
    float2 p0 = unpack2(acc[0]), p1 = unpack2(acc[1]);
    float2 p2 = unpack2(acc[2]), p3 = unpack2(acc[3]);
    ((float4*)g_agg2)[node * (HD / 4) + c * 2 + 0] =
        make_float4(p0.x * di, p0.y * di, p1.x * di, p1.y * di);
    ((float4*)g_agg2)[node * (HD / 4) + c * 2 + 1] =
        make_float4(p2.x * di, p2.y * di, p3.x * di, p3.y * di);
}

// ---- layer-2 dense (FFMA2): out = agg2@W2l + b2 + relu(bn(hpre))@W2r ----
#define NT2 32
__global__ void __launch_bounds__(64) k_lin2(const float* __restrict__ b2,
                                             float* __restrict__ out) {
    __shared__ float sg[NT2][HD];
    __shared__ float sh_[NT2][HD];
    const int n0 = blockIdx.x * NT2;
    const int tid = threadIdx.x;   // 64

    for (int idx = tid; idx < NT2 * (HD / 4); idx += 64) {
        int r = idx >> 5, c = idx & 31;
        int node = n0 + r;
        float4 vg = make_float4(0.f, 0.f, 0.f, 0.f), vh = vg;
        if (node < NN) {
            vg = ((const float4*)g_agg2)[node * 32 + c];
            float4 h  = ((const float4*)g_hpre)[node * 32 + c];
            float4 sc = ((const float4*)g_scale)[c];
            float4 sf = ((const float4*)g_shift)[c];
            vh.x = fmaxf(fmaf(h.x, sc.x, sf.x), 0.f);
            vh.y = fmaxf(fmaf(h.y, sc.y, sf.y), 0.f);
            vh.z = fmaxf(fmaf(h.z, sc.z, sf.z), 0.f);
            vh.w = fmaxf(fmaf(h.w, sc.w, sf.w), 0.f);
        }
        *(float4*)&sg[r][4 * c] = vg;
        *(float4*)&sh_[r][4 * c] = vh;
    }
    __syncthreads();

    const int j = tid;   // 0..63
    ull acc[NT2];
#pragma unroll
    for (int n = 0; n < NT2; n++) acc[n] = 0ull;

    for (int kq = 0; kq < HD / 4; kq++) {
        ull wl01 = g_w2l[(2 * kq) * OD + j];
        ull wl23 = g_w2l[(2 * kq + 1) * OD + j];
        ull wr01 = g_w2r[(2 * kq) * OD + j];
        ull wr23 = g_w2r[(2 * kq + 1) * OD + j];
#pragma unroll
        for (int n = 0; n < NT2; n++) {
            ulonglong2 a = *(const ulonglong2*)&sg[n][4 * kq];
            ulonglong2 h = *(const ulonglong2*)&sh_[n][4 * kq];
            ffma2(acc[n], a.x, wl01);
            ffma2(acc[n], a.y, wl23);
            ffma2(acc[n], h.x, wr01);
            ffma2(acc[n], h.y, wr23);
        }
    }

    const float bj = b2[j];
#pragma unroll
    for (int n = 0; n < NT2; n++) {
        int node = n0 + n;
        if (node < NN) {
            float2 p = unpack2(acc[n]);
            out[node * OD + j] = p.x + p.y + bj;
        }
    }
}

extern "C" void kernel_launch(void* const* d_in, const int* in_sizes, int n_in,
                              void* d_out, int out_size) {
    const float* x     = (const float*)d_in[0];
    const int*   ei    = (const int*)d_in[1];
    const float* W1l   = (const float*)d_in[2];
    const float* b1    = (const float*)d_in[3];
    const float* W1r   = (const float*)d_in[4];
    const float* gamma = (const float*)d_in[5];
    const float* beta  = (const float*)d_in[6];
    const float* W2l   = (const float*)d_in[7];
    const float* b2    = (const float*)d_in[8];
    const float* W2r   = (const float*)d_in[9];
    float* out = (float*)d_out;

    const int* src = ei;
    const int* dst = ei + NE;

    // one-time stream/event setup (host objects only; no device allocations)
    static cudaStream_t s2 = nullptr;
    static cudaEvent_t ev_fork = nullptr, ev_join = nullptr;
    if (s2 == nullptr) {
        cudaStreamCreateWithFlags(&s2, cudaStreamNonBlocking);
        cudaEventCreateWithFlags(&ev_fork, cudaEventDisableTiming);
        cudaEventCreateWithFlags(&ev_join, cudaEventDisableTiming);
    }

    // fork: prep (weights + fp16 x) on side stream, CSR chain on main stream
    cudaEventRecord(ev_fork, 0);
    cudaStreamWaitEvent(s2, ev_fork, 0);
    k_prep<<<1024, 256, 0, s2>>>(x, W1l, W1r, W2l, W2r);

    k_deg<<<(NE / 4 + 255) / 256, 256>>>(dst);
    k_scan1<<<NB, 1024>>>();
    k_scan3<<<NB, 1024>>>();
    k_fill<<<(NE / 4 + 255) / 256, 256>>>(src, dst);

    // join: agg1 needs both xh (side) and esrc/off/deginv (main)
    cudaEventRecord(ev_join, s2);
    cudaStreamWaitEvent(0, ev_join, 0);

    k_agg1<<<(NN * 8 + 255) / 256, 256>>>();
    k_lin1<<<(NN + NT1 - 1) / NT1, 128>>>(x, b1);
    k_hrelu<<<(NN * HD / 4 + 255) / 256, 256>>>(gamma, beta);
    k_agg2<<<(NN * 16 + 255) / 256, 256>>>();
    k_lin2<<<(NN + NT2 - 1) / NT2, 64>>>(b2, out);
}

// round 12
// speedup vs baseline: 1.3514x; 1.2662x over previous
#include <cuda_runtime.h>
#include <cuda_fp16.h>
#include <mma.h>
#include <cstdint>

using namespace nvcuda;

#define NN 50000
#define NN_PAD 50048   // 391 * 128
#define NE 800000
#define IND 64
#define HD 128
#define OD 64
#define BN_EPS 1e-5f
#define NB 49   // ceil(NN/1024)

typedef unsigned long long ull;

// ---- scratch (__device__ globals; zero-init at load; zero-invariants kept) ----
__device__ __align__(256) int    g_degi[NN];        // zero-invariant (restored in k_scan3)
__device__ __align__(256) int    g_off[NN + 1];
__device__ __align__(256) int    g_cur[NN];
__device__ __align__(256) int    g_esrc[NE];
__device__ __align__(256) int    g_bsums[NB];
__device__ __align__(256) float  g_deginv[NN];
__device__ __align__(256) __half g_xh[NN_PAD * IND];    // fp16 x (pad rows stay 0)
__device__ __align__(256) __half g_agg1h[NN_PAD * IND]; // fp16 mean-agg of x (pad 0)
__device__ __align__(256) float  g_hpre[NN_PAD * HD];   // fp32 pre-BN layer-1 out
__device__ __align__(256) __half g_hrelu[NN_PAD * HD];  // fp16 relu(bn(hpre)) (pad 0)
__device__ __align__(256) __half g_agg2h[NN_PAD * HD];  // fp16 mean-agg of hrelu (pad 0)
__device__ __align__(256) float  g_bnsum[HD];       // zero-invariant (restored in k_agg2)
__device__ __align__(256) float  g_bnsq[HD];        // zero-invariant (restored in k_agg2)
// fp16 weight matrices for WMMA, row-major [k][j]
__device__ __align__(256) __half g_wb1[HD * HD];    // k:[W1l rows 0..63 | W1r rows 64..127], N=128
__device__ __align__(256) __half g_wb2[2 * HD * OD];// k:[W2l rows 0..127 | W2r rows 128..255], N=64

__device__ __forceinline__ ull pack2(float x, float y) {
    ull r;
    asm("mov.b64 %0, {%1,%2};" : "=l"(r) : "f"(x), "f"(y));
    return r;
}
__device__ __forceinline__ float2 unpack2(ull v) {
    float2 r;
    asm("mov.b64 {%0,%1}, %2;" : "=f"(r.x), "=f"(r.y) : "l"(v));
    return r;
}
__device__ __forceinline__ void fadd2(ull& d, ull a) {
    asm("add.rn.f32x2 %0, %0, %1;" : "+l"(d) : "l"(a));
}
__device__ __forceinline__ void acc_u4(ull* acc, uint4 u) {
    float2 f0 = __half22float2(*(__half2*)&u.x);
    float2 f1 = __half22float2(*(__half2*)&u.y);
    float2 f2 = __half22float2(*(__half2*)&u.z);
    float2 f3 = __half22float2(*(__half2*)&u.w);
    fadd2(acc[0], pack2(f0.x, f0.y));
    fadd2(acc[1], pack2(f1.x, f1.y));
    fadd2(acc[2], pack2(f2.x, f2.y));
    fadd2(acc[3], pack2(f3.x, f3.y));
}
__device__ __forceinline__ uint4 f8_to_h8(const float* s) {
    __half2 a = __floats2half2_rn(s[0], s[1]);
    __half2 b = __floats2half2_rn(s[2], s[3]);
    __half2 c = __floats2half2_rn(s[4], s[5]);
    __half2 d = __floats2half2_rn(s[6], s[7]);
    uint4 u;
    u.x = *(unsigned int*)&a; u.y = *(unsigned int*)&b;
    u.z = *(unsigned int*)&c; u.w = *(unsigned int*)&d;
    return u;
}

// ---- fused prep + degree histogram ----
__global__ void k_prepdeg(const float* __restrict__ x,
                          const float* __restrict__ W1l, const float* __restrict__ W1r,
                          const float* __restrict__ W2l, const float* __restrict__ W2r,
                          const int* __restrict__ dst) {
    int t = blockIdx.x * blockDim.x + threadIdx.x;
    int stride = gridDim.x * blockDim.x;
    // WMMA B1: [k][j] row-major 128x128, k<64 -> W1l, else W1r
    for (int i = t; i < HD * HD; i += stride) {
        int k = i >> 7, j = i & 127;
        float w = (k < IND) ? W1l[k * HD + j] : W1r[(k - IND) * HD + j];
        g_wb1[i] = __float2half_rn(w);
    }
    // WMMA B2: [k][j] row-major 256x64, k<128 -> W2l, else W2r
    for (int i = t; i < 2 * HD * OD; i += stride) {
        int k = i >> 6, j = i & 63;
        float w = (k < HD) ? W2l[k * OD + j] : W2r[(k - HD) * OD + j];
        g_wb2[i] = __float2half_rn(w);
    }
    for (int i = t; i < NN * IND / 8; i += stride) {
        float4 v0 = ((const float4*)x)[2 * i];
        float4 v1 = ((const float4*)x)[2 * i + 1];
        float f[8] = {v0.x, v0.y, v0.z, v0.w, v1.x, v1.y, v1.z, v1.w};
        ((uint4*)g_xh)[i] = f8_to_h8(f);
    }
    for (int i = t; i < NE / 4; i += stride) {
        int4 d = ((const int4*)dst)[i];
        atomicAdd(&g_degi[d.x], 1);
        atomicAdd(&g_degi[d.y], 1);
        atomicAdd(&g_degi[d.z], 1);
        atomicAdd(&g_degi[d.w], 1);
    }
}

// ---- scan stage 1 ----
__global__ void k_scan1() {
    __shared__ int ws[32];
    int tid = threadIdx.x, lane = tid & 31, w = tid >> 5;
    int i = blockIdx.x * 1024 + tid;
    int v = (i < NN) ? g_degi[i] : 0;
    int s = v;
#pragma unroll
    for (int o = 1; o < 32; o <<= 1) {
        int tt = __shfl_up_sync(0xffffffffu, s, o);
        if (lane >= o) s += tt;
    }
    if (lane == 31) ws[w] = s;
    __syncthreads();
    if (w == 0) {
        int t2 = ws[lane];
#pragma unroll
        for (int o = 1; o < 32; o <<= 1) {
            int tt = __shfl_up_sync(0xffffffffu, t2, o);
            if (lane >= o) t2 += tt;
        }
        ws[lane] = t2;
    }
    __syncthreads();
    int excl = ((w > 0) ? ws[w - 1] : 0) + s - v;
    if (i < NN) g_off[i] = excl;
    if (tid == 1023) g_bsums[blockIdx.x] = ws[31];
}

// ---- scan stage 2: prefix + cursors + deginv + restore g_degi zeros ----
__global__ void k_scan3() {
    __shared__ int sb[64];
    int tid = threadIdx.x;
    if (tid < 64) {
        int lane = tid & 31;
        int v = (tid < NB) ? g_bsums[tid] : 0;
        int s = v;
#pragma unroll
        for (int o = 1; o < 32; o <<= 1) {
            int tt = __shfl_up_sync(0xffffffffu, s, o);
            if (lane >= o) s += tt;
        }
        sb[tid] = s - v;
    }
    __syncthreads();
    if (tid >= 32 && tid < 64) {
        int w0tot = sb[31] + g_bsums[31];
        sb[tid] += w0tot;
    }
    __syncthreads();
    int pref = sb[blockIdx.x];
    int i = blockIdx.x * 1024 + tid;
    if (i < NN) {
        int off = g_off[i] + pref;
        g_off[i] = off;
        g_cur[i] = off;
        int d = g_degi[i];
        g_deginv[i] = (d > 0) ? (1.0f / (float)d) : 0.0f;
        g_degi[i] = 0;
    }
    if (i == NN) g_off[NN] = NE;
}

// ---- CSR fill, 4 edges/thread ----
__global__ void k_fill(const int* __restrict__ src, const int* __restrict__ dst) {
    int t = blockIdx.x * blockDim.x + threadIdx.x;
    if (t * 4 >= NE) return;
    int4 s4 = ((const int4*)src)[t];
    int4 d4 = ((const int4*)dst)[t];
    int p0 = atomicAdd(&g_cur[d4.x], 1);
    int p1 = atomicAdd(&g_cur[d4.y], 1);
    int p2 = atomicAdd(&g_cur[d4.z], 1);
    int p3 = atomicAdd(&g_cur[d4.w], 1);
    g_esrc[p0] = s4.x;
    g_esrc[p1] = s4.y;
    g_esrc[p2] = s4.z;
    g_esrc[p3] = s4.w;
}

// ---- layer-1 mean aggregation: 8 threads/node, f32x2 accumulate, fp16 out ----
__global__ void k_agg1() {
    int t = blockIdx.x * blockDim.x + threadIdx.x;
    int node = t >> 3, c = t & 7;
    if (node >= NN) return;
    int beg = g_off[node], end = g_off[node + 1];
    ull acc[4] = {0ull, 0ull, 0ull, 0ull};
    int j = beg;
    for (; j + 2 <= end; j += 2) {
        int s0 = g_esrc[j], s1 = g_esrc[j + 1];
        uint4 u0 = ((const uint4*)g_xh)[s0 * 8 + c];
        uint4 u1 = ((const uint4*)g_xh)[s1 * 8 + c];
        acc_u4(acc, u0);
        acc_u4(acc, u1);
    }
    if (j < end)
        acc_u4(acc, ((const uint4*)g_xh)[g_esrc[j] * 8 + c]);
    float di = g_deginv[node];
    float2 p0 = unpack2(acc[0]), p1 = unpack2(acc[1]);
    float2 p2 = unpack2(acc[2]), p3 = unpack2(acc[3]);
    float f[8] = {p0.x * di, p0.y * di, p1.x * di, p1.y * di,
                  p2.x * di, p2.y * di, p3.x * di, p3.y * di};
    ((uint4*)g_agg1h)[node * 8 + c] = f8_to_h8(f);
}

// ==== layer-1 dense via WMMA (HMMA): hpre = [agg1h|xh] @ [W1l;W1r]
//      b1 omitted: BatchNorm is invariant to a per-feature constant shift. ====
__global__ void __launch_bounds__(256) k_lin1w() {
    __shared__ __half smB[HD * HD];   // 32 KB: B1 staged
    const int tid = threadIdx.x;
    const int warp = tid >> 5;
    const int m0 = blockIdx.x * 128 + warp * 16;

    for (int i = tid; i < HD * HD / 8; i += 256)
        ((uint4*)smB)[i] = ((const uint4*)g_wb1)[i];
    __syncthreads();

    wmma::fragment<wmma::accumulator, 16, 16, 16, float> acc[8];
#pragma unroll
    for (int n = 0; n < 8; n++) wmma::fill_fragment(acc[n], 0.0f);

#pragma unroll
    for (int k = 0; k < 4; k++) {   // K 0..63 from agg1h
        wmma::fragment<wmma::matrix_a, 16, 16, 16, __half, wmma::row_major> af;
        wmma::load_matrix_sync(af, g_agg1h + (size_t)m0 * IND + k * 16, IND);
#pragma unroll
        for (int n = 0; n < 8; n++) {
            wmma::fragment<wmma::matrix_b, 16, 16, 16, __half, wmma::row_major> bf;
            wmma::load_matrix_sync(bf, smB + (k * 16) * HD + n * 16, HD);
            wmma::mma_sync(acc[n], af, bf, acc[n]);
        }
    }
#pragma unroll
    for (int k = 0; k < 4; k++) {   // K 64..127 from xh
        wmma::fragment<wmma::matrix_a, 16, 16, 16, __half, wmma::row_major> af;
        wmma::load_matrix_sync(af, g_xh + (size_t)m0 * IND + k * 16, IND);
#pragma unroll
        for (int n = 0; n < 8; n++) {
            wmma::fragment<wmma::matrix_b, 16, 16, 16, __half, wmma::row_major> bf;
            wmma::load_matrix_sync(bf, smB + (64 + k * 16) * HD + n * 16, HD);
            wmma::mma_sync(acc[n], af, bf, acc[n]);
        }
    }
#pragma unroll
    for (int n = 0; n < 8; n++)
        wmma::store_matrix_sync(g_hpre + (size_t)m0 * HD + n * 16, acc[n], HD,
                                wmma::mem_row_major);
}

// ---- BN column statistics over hpre (valid rows only) ----
__global__ void k_bnstat() {
    int j = threadIdx.x & 127;
    int stream = blockIdx.x * 2 + (threadIdx.x >> 7);
    float s = 0.f, sq = 0.f;
    for (int n = stream; n < NN; n += 256) {
        float v = g_hpre[n * HD + j];
        s += v;
        sq += v * v;
    }
    atomicAdd(&g_bnsum[j], s);
    atomicAdd(&g_bnsq[j], sq);
}

// ---- BN finalize + relu: g_hrelu = fp16(relu(bn(hpre))) ----
__global__ void k_hrelu(const float* __restrict__ gamma,
                        const float* __restrict__ beta) {
    __shared__ float s_sc[HD];
    __shared__ float s_sh[HD];
    int tid = threadIdx.x;
    if (tid < HD) {
        float mu = g_bnsum[tid] * (1.0f / NN);
        float var = g_bnsq[tid] * (1.0f / NN) - mu * mu;
        float sc = gamma[tid] * rsqrtf(var + BN_EPS);
        s_sc[tid] = sc;
        s_sh[tid] = beta[tid] - mu * sc;
    }
    __syncthreads();
    int i = blockIdx.x * blockDim.x + tid;
    if (i >= NN * HD / 4) return;
    int c = i & 31;
    float4 h = ((const float4*)g_hpre)[i];
    float4 sc = *(const float4*)&s_sc[4 * c];
    float4 sh = *(const float4*)&s_sh[4 * c];
    float v0 = fmaxf(fmaf(h.x, sc.x, sh.x), 0.f);
    float v1 = fmaxf(fmaf(h.y, sc.y, sh.y), 0.f);
    float v2 = fmaxf(fmaf(h.z, sc.z, sh.z), 0.f);
    float v3 = fmaxf(fmaf(h.w, sc.w, sh.w), 0.f);
    __half2 a = __floats2half2_rn(v0, v1);
    __half2 b = __floats2half2_rn(v2, v3);
    uint2 u;
    u.x = *(unsigned int*)&a;
    u.y = *(unsigned int*)&b;
    ((uint2*)g_hrelu)[i] = u;
}

// ---- layer-2 mean aggregation: fp16 out; restores g_bnsum/g_bnsq zeros ----
__global__ void k_agg2() {
    int t = blockIdx.x * blockDim.x + threadIdx.x;
    if (t < HD) { g_bnsum[t] = 0.f; g_bnsq[t] = 0.f; }
    int node = t >> 4, c = t & 15;
    if (node >= NN) return;
    int beg = g_off[node], end = g_off[node + 1];
    ull acc[4] = {0ull, 0ull, 0ull, 0ull};
    int j = beg;
    for (; j + 2 <= end; j += 2) {
        int s0 = g_esrc[j], s1 = g_esrc[j + 1];
        uint4 u0 = ((const uint4*)g_hrelu)[s0 * 16 + c];
        uint4 u1 = ((const uint4*)g_hrelu)[s1 * 16 + c];
        acc_u4(acc, u0);
        acc_u4(acc, u1);
    }
    if (j < end)
        acc_u4(acc, ((const uint4*)g_hrelu)[g_esrc[j] * 16 + c]);
    float di = g_deginv[node];
    float2 p0 = unpack2(acc[0]), p1 = unpack2(acc[1]);
    float2 p2 = unpack2(acc[2]), p3 = unpack2(acc[3]);
    float f[8] = {p0.x * di, p0.y * di, p1.x * di, p1.y * di,
                  p2.x * di, p2.y * di, p3.x * di, p3.y * di};
    ((uint4*)g_agg2h)[node * 16 + c] = f8_to_h8(f);
}

// ==== layer-2 dense via WMMA: out = [agg2h|hrelu] @ [W2l;W2r] + b2 ====
__global__ void __launch_bounds__(256) k_lin2w(const float* __restrict__ b2,
                                               float* __restrict__ out) {
    __shared__ __half smB[2 * HD * OD];   // 32 KB: B2 staged (reused for C staging)
    const int tid = threadIdx.x;
    const int warp = tid >> 5, lane = tid & 31;
    const int m0 = blockIdx.x * 128 + warp * 16;

    for (int i = tid; i < 2 * HD * OD / 8; i += 256)
        ((uint4*)smB)[i] = ((const uint4*)g_wb2)[i];
    __syncthreads();

    wmma::fragment<wmma::accumulator, 16, 16, 16, float> acc[4];
#pragma unroll
    for (int n = 0; n < 4; n++) wmma::fill_fragment(acc[n], 0.0f);

#pragma unroll
    for (int k = 0; k < 8; k++) {   // K 0..127 from agg2h
        wmma::fragment<wmma::matrix_a, 16, 16, 16, __half, wmma::row_major> af;
        wmma::load_matrix_sync(af, g_agg2h + (size_t)m0 * HD + k * 16, HD);
#pragma unroll
        for (int n = 0; n < 4; n++) {
            wmma::fragment<wmma::matrix_b, 16, 16, 16, __half, wmma::row_major> bf;
            wmma::load_matrix_sync(bf, smB + (k * 16) * OD + n * 16, OD);
            wmma::mma_sync(acc[n], af, bf, acc[n]);
        }
    }
#pragma unroll
    for (int k = 0; k < 8; k++) {   // K 128..255 from hrelu
        wmma::fragment<wmma::matrix_a, 16, 16, 16, __half, wmma::row_major> af;
        wmma::load_matrix_sync(af, g_hrelu + (size_t)m0 * HD + k * 16, HD);
#pragma unroll
        for (int n = 0; n < 4; n++) {
            wmma::fragment<wmma::matrix_b, 16, 16, 16, __half, wmma::row_major> bf;
            wmma::load_matrix_sync(bf, smB + (128 + k * 16) * OD + n * 16, OD);
            wmma::mma_sync(acc[n], af, bf, acc[n]);
        }
    }

    // reuse smB as per-warp fp32 C staging (16x64 floats per warp = 4 KB)
    __syncthreads();
    float* cw = (float*)smB + warp * 16 * OD;
#pragma unroll
    for (int n = 0; n < 4; n++)
        wmma::store_matrix_sync(cw + n * 16, acc[n], OD, wmma::mem_row_major);
    __syncwarp();

    float bj0 = b2[lane];
    float bj1 = b2[lane + 32];
#pragma unroll
    for (int r = 0; r < 16; r++) {
        int node = m0 + r;
        if (node < NN) {
            out[node * OD + lane]      = cw[r * OD + lane] + bj0;
            out[node * OD + lane + 32] = cw[r * OD + lane + 32] + bj1;
        }
    }
}

extern "C" void kernel_launch(void* const* d_in, const int* in_sizes, int n_in,
                              void* d_out, int out_size) {
    const float* x     = (const float*)d_in[0];
    const int*   ei    = (const int*)d_in[1];
    const float* W1l   = (const float*)d_in[2];
    const float* b1    = (const float*)d_in[3];
    const float* W1r   = (const float*)d_in[4];
    const float* gamma = (const float*)d_in[5];
    const float* beta  = (const float*)d_in[6];
    const float* W2l   = (const float*)d_in[7];
    const float* b2    = (const float*)d_in[8];
    const float* W2r   = (const float*)d_in[9];
    float* out = (float*)d_out;
    (void)b1;   // BN makes the layer-1 bias a no-op

    const int* src = ei;
    const int* dst = ei + NE;

    k_prepdeg<<<2048, 256>>>(x, W1l, W1r, W2l, W2r, dst);
    k_scan1<<<NB, 1024>>>();
    k_scan3<<<NB, 1024>>>();
    k_fill<<<(NE / 4 + 255) / 256, 256>>>(src, dst);
    k_agg1<<<(NN * 8 + 255) / 256, 256>>>();
    k_lin1w<<<NN_PAD / 128, 256>>>();
    k_bnstat<<<128, 256>>>();
    k_hrelu<<<(NN * HD / 4 + 255) / 256, 256>>>(gamma, beta);
    k_agg2<<<(NN * 16 + 255) / 256, 256>>>();
    k_lin2w<<<NN_PAD / 128, 256>>>(b2, out);
}

// round 13
// speedup vs baseline: 1.4312x; 1.0590x over previous
#include <cuda_runtime.h>
#include <cuda_fp16.h>
#include <mma.h>
#include <cstdint>

using namespace nvcuda;

#define NN 50000
#define NN_PAD 50048   // 391 * 128
#define NE 800000
#define IND 64
#define HD 128
#define OD 64
#define BN_EPS 1e-5f
#define NB 49   // ceil(NN/1024)

typedef unsigned long long ull;

// ---- scratch (__device__ globals; zero-init at load; zero-invariants kept) ----
__device__ __align__(256) int    g_degi[NN];        // zero-invariant (restored in k_scan3)
__device__ __align__(256) int    g_off[NN + 1];
__device__ __align__(256) int    g_rank[NE];        // edge rank within its dst bucket
__device__ __align__(256) int    g_esrc[NE];
__device__ __align__(256) int    g_bsums[NB];
__device__ __align__(256) float  g_deginv[NN];
__device__ __align__(256) __half g_xh[NN_PAD * IND];    // fp16 x (pad rows stay 0)
__device__ __align__(256) __half g_agg1h[NN_PAD * IND]; // fp16 mean-agg of x (pad 0)
__device__ __align__(256) float  g_hpre[NN_PAD * HD];   // fp32 pre-BN layer-1 out
__device__ __align__(256) __half g_hrelu[NN_PAD * HD];  // fp16 relu(bn(hpre)) (pad 0)
__device__ __align__(256) __half g_agg2h[NN_PAD * HD];  // fp16 mean-agg of hrelu (pad 0)
__device__ __align__(256) float  g_bnsum[HD];       // zero-invariant (restored in k_agg2)
__device__ __align__(256) float  g_bnsq[HD];        // zero-invariant (restored in k_agg2)
// fp16 weight matrices for WMMA, row-major [k][j]
__device__ __align__(256) __half g_wb1[HD * HD];    // k:[W1l rows 0..63 | W1r rows 64..127], N=128
__device__ __align__(256) __half g_wb2[2 * HD * OD];// k:[W2l rows 0..127 | W2r rows 128..255], N=64

__device__ __forceinline__ ull pack2(float x, float y) {
    ull r;
    asm("mov.b64 %0, {%1,%2};" : "=l"(r) : "f"(x), "f"(y));
    return r;
}
__device__ __forceinline__ float2 unpack2(ull v) {
    float2 r;
    asm("mov.b64 {%0,%1}, %2;" : "=f"(r.x), "=f"(r.y) : "l"(v));
    return r;
}
__device__ __forceinline__ void fadd2(ull& d, ull a) {
    asm("add.rn.f32x2 %0, %0, %1;" : "+l"(d) : "l"(a));
}
__device__ __forceinline__ void acc_u4(ull* acc, uint4 u) {
    float2 f0 = __half22float2(*(__half2*)&u.x);
    float2 f1 = __half22float2(*(__half2*)&u.y);
    float2 f2 = __half22float2(*(__half2*)&u.z);
    float2 f3 = __half22float2(*(__half2*)&u.w);
    fadd2(acc[0], pack2(f0.x, f0.y));
    fadd2(acc[1], pack2(f1.x, f1.y));
    fadd2(acc[2], pack2(f2.x, f2.y));
    fadd2(acc[3], pack2(f3.x, f3.y));
}
__device__ __forceinline__ uint4 f8_to_h8(const float* s) {
    __half2 a = __floats2half2_rn(s[0], s[1]);
    __half2 b = __floats2half2_rn(s[2], s[3]);
    __half2 c = __floats2half2_rn(s[4], s[5]);
    __half2 d = __floats2half2_rn(s[6], s[7]);
    uint4 u;
    u.x = *(unsigned int*)&a; u.y = *(unsigned int*)&b;
    u.z = *(unsigned int*)&c; u.w = *(unsigned int*)&d;
    return u;
}

// ---- fused prep + degree histogram (stores per-edge rank = old count) ----
__global__ void k_prepdeg(const float* __restrict__ x,
                          const float* __restrict__ W1l, const float* __restrict__ W1r,
                          const float* __restrict__ W2l, const float* __restrict__ W2r,
                          const int* __restrict__ dst) {
    int t = blockIdx.x * blockDim.x + threadIdx.x;
    int stride = gridDim.x * blockDim.x;
    // WMMA B1: [k][j] row-major 128x128, k<64 -> W1l, else W1r
    for (int i = t; i < HD * HD; i += stride) {
        int k = i >> 7, j = i & 127;
        float w = (k < IND) ? W1l[k * HD + j] : W1r[(k - IND) * HD + j];
        g_wb1[i] = __float2half_rn(w);
    }
    // WMMA B2: [k][j] row-major 256x64, k<128 -> W2l, else W2r
    for (int i = t; i < 2 * HD * OD; i += stride) {
        int k = i >> 6, j = i & 63;
        float w = (k < HD) ? W2l[k * OD + j] : W2r[(k - HD) * OD + j];
        g_wb2[i] = __float2half_rn(w);
    }
    for (int i = t; i < NN * IND / 8; i += stride) {
        float4 v0 = ((const float4*)x)[2 * i];
        float4 v1 = ((const float4*)x)[2 * i + 1];
        float f[8] = {v0.x, v0.y, v0.z, v0.w, v1.x, v1.y, v1.z, v1.w};
        ((uint4*)g_xh)[i] = f8_to_h8(f);
    }
    for (int i = t; i < NE / 4; i += stride) {
        int4 d = ((const int4*)dst)[i];
        int4 r;
        r.x = atomicAdd(&g_degi[d.x], 1);
        r.y = atomicAdd(&g_degi[d.y], 1);
        r.z = atomicAdd(&g_degi[d.z], 1);
        r.w = atomicAdd(&g_degi[d.w], 1);
        ((int4*)g_rank)[i] = r;
    }
}

// ---- scan stage 1 ----
__global__ void k_scan1() {
    __shared__ int ws[32];
    int tid = threadIdx.x, lane = tid & 31, w = tid >> 5;
    int i = blockIdx.x * 1024 + tid;
    int v = (i < NN) ? g_degi[i] : 0;
    int s = v;
#pragma unroll
    for (int o = 1; o < 32; o <<= 1) {
        int tt = __shfl_up_sync(0xffffffffu, s, o);
        if (lane >= o) s += tt;
    }
    if (lane == 31) ws[w] = s;
    __syncthreads();
    if (w == 0) {
        int t2 = ws[lane];
#pragma unroll
        for (int o = 1; o < 32; o <<= 1) {
            int tt = __shfl_up_sync(0xffffffffu, t2, o);
            if (lane >= o) t2 += tt;
        }
        ws[lane] = t2;
    }
    __syncthreads();
    int excl = ((w > 0) ? ws[w - 1] : 0) + s - v;
    if (i < NN) g_off[i] = excl;
    if (tid == 1023) g_bsums[blockIdx.x] = ws[31];
}

// ---- scan stage 2: prefix + deginv + restore g_degi zeros ----
__global__ void k_scan3() {
    __shared__ int sb[64];
    int tid = threadIdx.x;
    if (tid < 64) {
        int lane = tid & 31;
        int v = (tid < NB) ? g_bsums[tid] : 0;
        int s = v;
#pragma unroll
        for (int o = 1; o < 32; o <<= 1) {
            int tt = __shfl_up_sync(0xffffffffu, s, o);
            if (lane >= o) s += tt;
        }
        sb[tid] = s - v;
    }
    __syncthreads();
    if (tid >= 32 && tid < 64) {
        int w0tot = sb[31] + g_bsums[31];
        sb[tid] += w0tot;
    }
    __syncthreads();
    int pref = sb[blockIdx.x];
    int i = blockIdx.x * 1024 + tid;
    if (i < NN) {
        g_off[i] += pref;
        int d = g_degi[i];
        g_deginv[i] = (d > 0) ? (1.0f / (float)d) : 0.0f;
        g_degi[i] = 0;
    }
    if (i == NN) g_off[NN] = NE;
}

// ---- CSR fill, atomic-free: pos = off[dst] + rank, 4 edges/thread ----
__global__ void k_fill(const int* __restrict__ src, const int* __restrict__ dst) {
    int t = blockIdx.x * blockDim.x + threadIdx.x;
    if (t * 4 >= NE) return;
    int4 s4 = ((const int4*)src)[t];
    int4 d4 = ((const int4*)dst)[t];
    int4 r4 = ((const int4*)g_rank)[t];
    g_esrc[g_off[d4.x] + r4.x] = s4.x;
    g_esrc[g_off[d4.y] + r4.y] = s4.y;
    g_esrc[g_off[d4.z] + r4.z] = s4.z;
    g_esrc[g_off[d4.w] + r4.w] = s4.w;
}

// ---- layer-1 mean aggregation: 8 threads/node, f32x2 accumulate, fp16 out ----
__global__ void k_agg1() {
    int t = blockIdx.x * blockDim.x + threadIdx.x;
    int node = t >> 3, c = t & 7;
    if (node >= NN) return;
    int beg = g_off[node], end = g_off[node + 1];
    ull acc[4] = {0ull, 0ull, 0ull, 0ull};
    int j = beg;
    for (; j + 2 <= end; j += 2) {
        int s0 = g_esrc[j], s1 = g_esrc[j + 1];
        uint4 u0 = ((const uint4*)g_xh)[s0 * 8 + c];
        uint4 u1 = ((const uint4*)g_xh)[s1 * 8 + c];
        acc_u4(acc, u0);
        acc_u4(acc, u1);
    }
    if (j < end)
        acc_u4(acc, ((const uint4*)g_xh)[g_esrc[j] * 8 + c]);
    float di = g_deginv[node];
    float2 p0 = unpack2(acc[0]), p1 = unpack2(acc[1]);
    float2 p2 = unpack2(acc[2]), p3 = unpack2(acc[3]);
    float f[8] = {p0.x * di, p0.y * di, p1.x * di, p1.y * di,
                  p2.x * di, p2.y * di, p3.x * di, p3.y * di};
    ((uint4*)g_agg1h)[node * 8 + c] = f8_to_h8(f);
}

// ==== layer-1 dense via WMMA (HMMA): hpre = [agg1h|xh] @ [W1l;W1r]
//      b1 omitted: BatchNorm is invariant to a per-feature constant shift. ====
__global__ void __launch_bounds__(256) k_lin1w() {
    __shared__ __half smB[HD * HD];   // 32 KB: B1 staged
    const int tid = threadIdx.x;
    const int warp = tid >> 5;
    const int m0 = blockIdx.x * 128 + warp * 16;

    for (int i = tid; i < HD * HD / 8; i += 256)
        ((uint4*)smB)[i] = ((const uint4*)g_wb1)[i];
    __syncthreads();

    wmma::fragment<wmma::accumulator, 16, 16, 16, float> acc[8];
#pragma unroll
    for (int n = 0; n < 8; n++) wmma::fill_fragment(acc[n], 0.0f);

#pragma unroll
    for (int k = 0; k < 4; k++) {   // K 0..63 from agg1h
        wmma::fragment<wmma::matrix_a, 16, 16, 16, __half, wmma::row_major> af;
        wmma::load_matrix_sync(af, g_agg1h + (size_t)m0 * IND + k * 16, IND);
#pragma unroll
        for (int n = 0; n < 8; n++) {
            wmma::fragment<wmma::matrix_b, 16, 16, 16, __half, wmma::row_major> bf;
            wmma::load_matrix_sync(bf, smB + (k * 16) * HD + n * 16, HD);
            wmma::mma_sync(acc[n], af, bf, acc[n]);
        }
    }
#pragma unroll
    for (int k = 0; k < 4; k++) {   // K 64..127 from xh
        wmma::fragment<wmma::matrix_a, 16, 16, 16, __half, wmma::row_major> af;
        wmma::load_matrix_sync(af, g_xh + (size_t)m0 * IND + k * 16, IND);
#pragma unroll
        for (int n = 0; n < 8; n++) {
            wmma::fragment<wmma::matrix_b, 16, 16, 16, __half, wmma::row_major> bf;
            wmma::load_matrix_sync(bf, smB + (64 + k * 16) * HD + n * 16, HD);
            wmma::mma_sync(acc[n], af, bf, acc[n]);
        }
    }
#pragma unroll
    for (int n = 0; n < 8; n++)
        wmma::store_matrix_sync(g_hpre + (size_t)m0 * HD + n * 16, acc[n], HD,
                                wmma::mem_row_major);
}

// ---- BN column statistics over hpre (valid rows only) ----
__global__ void k_bnstat() {
    int j = threadIdx.x & 127;
    int stream = blockIdx.x * 2 + (threadIdx.x >> 7);
    float s = 0.f, sq = 0.f;
    for (int n = stream; n < NN; n += 256) {
        float v = g_hpre[n * HD + j];
        s += v;
        sq += v * v;
    }
    atomicAdd(&g_bnsum[j], s);
    atomicAdd(&g_bnsq[j], sq);
}

// ---- BN finalize + relu: g_hrelu = fp16(relu(bn(hpre))) ----
__global__ void k_hrelu(const float* __restrict__ gamma,
                        const float* __restrict__ beta) {
    __shared__ float s_sc[HD];
    __shared__ float s_sh[HD];
    int tid = threadIdx.x;
    if (tid < HD) {
        float mu = g_bnsum[tid] * (1.0f / NN);
        float var = g_bnsq[tid] * (1.0f / NN) - mu * mu;
        float sc = gamma[tid] * rsqrtf(var + BN_EPS);
        s_sc[tid] = sc;
        s_sh[tid] = beta[tid] - mu * sc;
    }
    __syncthreads();
    int i = blockIdx.x * blockDim.x + tid;
    if (i >= NN * HD / 4) return;
    int c = i & 31;
    float4 h = ((const float4*)g_hpre)[i];
    float4 sc = *(const float4*)&s_sc[4 * c];
    float4 sh = *(const float4*)&s_sh[4 * c];
    float v0 = fmaxf(fmaf(h.x, sc.x, sh.x), 0.f);
    float v1 = fmaxf(fmaf(h.y, sc.y, sh.y), 0.f);
    float v2 = fmaxf(fmaf(h.z, sc.z, sh.z), 0.f);
    float v3 = fmaxf(fmaf(h.w, sc.w, sh.w), 0.f);
    __half2 a = __floats2half2_rn(v0, v1);
    __half2 b = __floats2half2_rn(v2, v3);
    uint2 u;
    u.x = *(unsigned int*)&a;
    u.y = *(unsigned int*)&b;
    ((uint2*)g_hrelu)[i] = u;
}

// ---- layer-2 mean aggregation: fp16 out; restores g_bnsum/g_bnsq zeros ----
__global__ void k_agg2() {
    int t = blockIdx.x * blockDim.x + threadIdx.x;
    if (t < HD) { g_bnsum[t] = 0.f; g_bnsq[t] = 0.f; }
    int node = t >> 4, c = t & 15;
    if (node >= NN) return;
    int beg = g_off[node], end = g_off[node + 1];
    ull acc[4] = {0ull, 0ull, 0ull, 0ull};
    int j = beg;
    for (; j + 2 <= end; j += 2) {
        int s0 = g_esrc[j], s1 = g_esrc[j + 1];
        uint4 u0 = ((const uint4*)g_hrelu)[s0 * 16 + c];
        uint4 u1 = ((const uint4*)g_hrelu)[s1 * 16 + c];
        acc_u4(acc, u0);
        acc_u4(acc, u1);
    }
    if (j < end)
        acc_u4(acc, ((const uint4*)g_hrelu)[g_esrc[j] * 16 + c]);
    float di = g_deginv[node];
    float2 p0 = unpack2(acc[0]), p1 = unpack2(acc[1]);
    float2 p2 = unpack2(acc[2]), p3 = unpack2(acc[3]);
    float f[8] = {p0.x * di, p0.y * di, p1.x * di, p1.y * di,
                  p2.x * di, p2.y * di, p3.x * di, p3.y * di};
    ((uint4*)g_agg2h)[node * 16 + c] = f8_to_h8(f);
}

// ==== layer-2 dense via WMMA: out = [agg2h|hrelu] @ [W2l;W2r] + b2 ====
__global__ void __launch_bounds__(256) k_lin2w(const float* __restrict__ b2,
                                               float* __restrict__ out) {
    __shared__ __half smB[2 * HD * OD];   // 32 KB: B2 staged (reused for C staging)
    const int tid = threadIdx.x;
    const int warp = tid >> 5, lane = tid & 31;
    const int m0 = blockIdx.x * 128 + warp * 16;

    for (int i = tid; i < 2 * HD * OD / 8; i += 256)
        ((uint4*)smB)[i] = ((const uint4*)g_wb2)[i];
    __syncthreads();

    wmma::fragment<wmma::accumulator, 16, 16, 16, float> acc[4];
#pragma unroll
    for (int n = 0; n < 4; n++) wmma::fill_fragment(acc[n], 0.0f);

#pragma unroll
    for (int k = 0; k < 8; k++) {   // K 0..127 from agg2h
        wmma::fragment<wmma::matrix_a, 16, 16, 16, __half, wmma::row_major> af;
        wmma::load_matrix_sync(af, g_agg2h + (size_t)m0 * HD + k * 16, HD);
#pragma unroll
        for (int n = 0; n < 4; n++) {
            wmma::fragment<wmma::matrix_b, 16, 16, 16, __half, wmma::row_major> bf;
            wmma::load_matrix_sync(bf, smB + (k * 16) * OD + n * 16, OD);
            wmma::mma_sync(acc[n], af, bf, acc[n]);
        }
    }
#pragma unroll
    for (int k = 0; k < 8; k++) {   // K 128..255 from hrelu
        wmma::fragment<wmma::matrix_a, 16, 16, 16, __half, wmma::row_major> af;
        wmma::load_matrix_sync(af, g_hrelu + (size_t)m0 * HD + k * 16, HD);
#pragma unroll
        for (int n = 0; n < 4; n++) {
            wmma::fragment<wmma::matrix_b, 16, 16, 16, __half, wmma::row_major> bf;
            wmma::load_matrix_sync(bf, smB + (128 + k * 16) * OD + n * 16, OD);
            wmma::mma_sync(acc[n], af, bf, acc[n]);
        }
    }

    // reuse smB as per-warp fp32 C staging (16x64 floats per warp = 4 KB)
    __syncthreads();
    float* cw = (float*)smB + warp * 16 * OD;
#pragma unroll
    for (int n = 0; n < 4; n++)
        wmma::store_matrix_sync(cw + n * 16, acc[n], OD, wmma::mem_row_major);
    __syncwarp();

    float bj0 = b2[lane];
    float bj1 = b2[lane + 32];
#pragma unroll
    for (int r = 0; r < 16; r++) {
        int node = m0 + r;
        if (node < NN) {
            out[node * OD + lane]      = cw[r * OD + lane] + bj0;
            out[node * OD + lane + 32] = cw[r * OD + lane + 32] + bj1;
        }
    }
}

extern "C" void kernel_launch(void* const* d_in, const int* in_sizes, int n_in,
                              void* d_out, int out_size) {
    const float* x     = (const float*)d_in[0];
    const int*   ei    = (const int*)d_in[1];
    const float* W1l   = (const float*)d_in[2];
    const float* b1    = (const float*)d_in[3];
    const float* W1r   = (const float*)d_in[4];
    const float* gamma = (const float*)d_in[5];
    const float* beta  = (const float*)d_in[6];
    const float* W2l   = (const float*)d_in[7];
    const float* b2    = (const float*)d_in[8];
    const float* W2r   = (const float*)d_in[9];
    float* out = (float*)d_out;
    (void)b1;   // BN makes the layer-1 bias a no-op

    const int* src = ei;
    const int* dst = ei + NE;

    k_prepdeg<<<2048, 256>>>(x, W1l, W1r, W2l, W2r, dst);
    k_scan1<<<NB, 1024>>>();
    k_scan3<<<NB, 1024>>>();
    k_fill<<<(NE / 4 + 255) / 256, 256>>>(src, dst);
    k_agg1<<<(NN * 8 + 255) / 256, 256>>>();
    k_lin1w<<<NN_PAD / 128, 256>>>();
    k_bnstat<<<128, 256>>>();
    k_hrelu<<<(NN * HD / 4 + 255) / 256, 256>>>(gamma, beta);
    k_agg2<<<(NN * 16 + 255) / 256, 256>>>();
    k_lin2w<<<NN_PAD / 128, 256>>>(b2, out);
}